// round 2
// baseline (speedup 1.0000x reference)
#include <cuda_runtime.h>

#define B_ 32
#define N_ 65536
#define CHUNKS 32          // blocks per batch in pass1
#define TPB 256

// Deterministic per-block partials: [b][block][27]  (21 sym H_eff + 6 g_eff)
__device__ float g_part[B_][CHUNKS][27];
// Per-point scratch: [b][n][8] = ti[6] (= inv*H_pd), s (= inv*g_d), pad
__device__ float g_scratch[(size_t)B_ * N_ * 8];

// ---------------------------------------------------------------------------
// Pass 1: single sweep over inputs (streaming loads, evict-first in L2 so the
// scratch we write stays L2-resident for pass 2). 2 points per iteration so
// every load is an LDG.128.
// ---------------------------------------------------------------------------
__global__ __launch_bounds__(TPB) void pass1_kernel(
    const float* __restrict__ r, const float* __restrict__ w,
    const float* __restrict__ Jp, const float* __restrict__ Jd,
    const float* __restrict__ lmbda)
{
    const int b = blockIdx.y;
    const float lam = __ldg(lmbda);

    float acc[27];
#pragma unroll
    for (int v = 0; v < 27; v++) acc[v] = 0.f;

    const int gidx   = blockIdx.x * TPB + threadIdx.x;   // pair index
    const int stride = CHUNKS * TPB;
    const size_t base4  = (size_t)b * N_ * 2;            // float index, k-pairs
    const size_t base24 = (size_t)b * N_ * 12;

    for (int idx = gidx; idx < N_ / 2; idx += stride) {
        // two consecutive points (n = 2*idx, 2*idx+1), k interleaved
        const float4 rv = __ldcs((const float4*)(r  + base4 + 4 * (size_t)idx));
        const float4 wv = __ldcs((const float4*)(w  + base4 + 4 * (size_t)idx));
        const float4 dv = __ldcs((const float4*)(Jd + base4 + 4 * (size_t)idx));
        const float4* jp4 = (const float4*)(Jp + base24 + 24 * (size_t)idx);
        float4 j0 = __ldcs(jp4 + 0), j1 = __ldcs(jp4 + 1), j2 = __ldcs(jp4 + 2);
        float4 j3 = __ldcs(jp4 + 3), j4 = __ldcs(jp4 + 4), j5 = __ldcs(jp4 + 5);

        float4* sc = (float4*)(g_scratch + ((size_t)b * N_ + 2 * (size_t)idx) * 8);

        float rr[2][2] = {{rv.x, rv.y}, {rv.z, rv.w}};
        float ww[2][2] = {{wv.x, wv.y}, {wv.z, wv.w}};
        float dd[2][2] = {{dv.x, dv.y}, {dv.z, dv.w}};
        float pj[2][2][6] = {
            {{j0.x, j0.y, j0.z, j0.w, j1.x, j1.y}, {j1.z, j1.w, j2.x, j2.y, j2.z, j2.w}},
            {{j3.x, j3.y, j3.z, j3.w, j4.x, j4.y}, {j4.z, j4.w, j5.x, j5.y, j5.z, j5.w}}};

#pragma unroll
        for (int p = 0; p < 2; p++) {
            const float wd0 = ww[p][0] * dd[p][0], wd1 = ww[p][1] * dd[p][1];
            const float wr0 = ww[p][0] * rr[p][0], wr1 = ww[p][1] * rr[p][1];
            const float Hdd = dd[p][0] * wd0 + dd[p][1] * wd1 + lam;
            const float gd  = rr[p][0] * wd0 + rr[p][1] * wd1;
            const float inv = 1.f / (Hdd + 1e-8f);
            const float s   = inv * gd;

            const float* p0 = pj[p][0];
            const float* p1 = pj[p][1];

            float hpd[6], ti[6];
#pragma unroll
            for (int i = 0; i < 6; i++) {
                hpd[i] = p0[i] * wd0 + p1[i] * wd1;
                ti[i]  = hpd[i] * inv;
            }

            // scratch (default caching -> stays in L2)
            sc[2 * p + 0] = make_float4(ti[0], ti[1], ti[2], ti[3]);
            sc[2 * p + 1] = make_float4(ti[4], ti[5], s, 0.f);

            int c = 0;
#pragma unroll
            for (int i = 0; i < 6; i++) {
                const float qi0 = p0[i] * ww[p][0], qi1 = p1[i] * ww[p][1];
#pragma unroll
                for (int j = i; j < 6; j++, c++)
                    acc[c] += qi0 * p0[j] + qi1 * p1[j] - ti[i] * hpd[j];
                acc[21 + i] += p0[i] * wr0 + p1[i] * wr1 - hpd[i] * gd * inv;
            }
        }
    }

    // warp reduce all 27
#pragma unroll
    for (int v = 0; v < 27; v++)
#pragma unroll
        for (int off = 16; off; off >>= 1)
            acc[v] += __shfl_down_sync(0xffffffffu, acc[v], off);

    __shared__ float swarp[TPB / 32][27];
    const int wid = threadIdx.x >> 5, lid = threadIdx.x & 31;
    if (lid == 0) {
#pragma unroll
        for (int v = 0; v < 27; v++) swarp[wid][v] = acc[v];
    }
    __syncthreads();
    if (threadIdx.x < 27) {
        float s = 0.f;
#pragma unroll
        for (int wv = 0; wv < TPB / 32; wv++) s += swarp[wv][threadIdx.x];
        g_part[b][blockIdx.x][threadIdx.x] = s;  // deterministic, no atomics
    }
}

// ---------------------------------------------------------------------------
// Solve: 32 threads, one 6x6 system each (double, partial pivoting).
// ---------------------------------------------------------------------------
__global__ void solve_kernel(const float* __restrict__ lmbda,
                             float* __restrict__ out_pose)
{
    const int b = threadIdx.x;
    if (b >= B_) return;
    const float lam = __ldg(lmbda);

    float sum[27];
#pragma unroll
    for (int v = 0; v < 27; v++) {
        float s = 0.f;
        for (int c = 0; c < CHUNKS; c++) s += g_part[b][c][v];
        sum[v] = s;
    }

    double A[6][7];
    int c = 0;
    for (int i = 0; i < 6; i++)
        for (int j = i; j < 6; j++, c++) { A[i][j] = sum[c]; A[j][i] = sum[c]; }
    for (int i = 0; i < 6; i++) {
        A[i][i] += (double)lam + 1e-4;   // lambda*I (H_pp) + eps*I (H_eff)
        A[i][6]  = sum[21 + i];          // g_eff
    }

    for (int col = 0; col < 6; col++) {
        int p = col;
        double mx = fabs(A[col][col]);
        for (int rr = col + 1; rr < 6; rr++) {
            double v = fabs(A[rr][col]);
            if (v > mx) { mx = v; p = rr; }
        }
        if (p != col)
            for (int j = col; j < 7; j++) {
                double t = A[col][j]; A[col][j] = A[p][j]; A[p][j] = t;
            }
        double pinv = 1.0 / A[col][col];
        for (int rr = col + 1; rr < 6; rr++) {
            double f = A[rr][col] * pinv;
            for (int j = col; j < 7; j++) A[rr][j] -= f * A[col][j];
        }
    }
    double x[6];
    for (int i = 5; i >= 0; i--) {
        double s = A[i][6];
        for (int j = i + 1; j < 6; j++) s -= A[i][j] * x[j];
        x[i] = s / A[i][i];
    }
    for (int i = 0; i < 6; i++) out_pose[b * 6 + i] = (float)x[i];
}

// ---------------------------------------------------------------------------
// Pass 2: delta_depth = s - ti . delta_pose   (scratch should be L2-hot)
// ---------------------------------------------------------------------------
__global__ __launch_bounds__(256) void pass2_kernel(
    const float* __restrict__ pose, float* __restrict__ depth)
{
    const int b = blockIdx.y;
    __shared__ float dp[6];
    if (threadIdx.x < 6) dp[threadIdx.x] = pose[b * 6 + threadIdx.x];
    __syncthreads();

    const int idx = blockIdx.x * blockDim.x + threadIdx.x;   // pair index
    if (idx < N_ / 2) {
        const float4* sc = (const float4*)(g_scratch + ((size_t)b * N_ + 2 * (size_t)idx) * 8);
        float4 a0 = __ldcs(sc + 0), a1 = __ldcs(sc + 1);
        float4 a2 = __ldcs(sc + 2), a3 = __ldcs(sc + 3);
        float2 out;
        out.x = a1.z - (a0.x * dp[0] + a0.y * dp[1] + a0.z * dp[2] +
                        a0.w * dp[3] + a1.x * dp[4] + a1.y * dp[5]);
        out.y = a3.z - (a2.x * dp[0] + a2.y * dp[1] + a2.z * dp[2] +
                        a2.w * dp[3] + a3.x * dp[4] + a3.y * dp[5]);
        __stcs((float2*)(depth + (size_t)b * N_ + 2 * (size_t)idx), out);
    }
}

// ---------------------------------------------------------------------------
extern "C" void kernel_launch(void* const* d_in, const int* in_sizes, int n_in,
                              void* d_out, int out_size)
{
    const float* r  = (const float*)d_in[0];
    const float* w  = (const float*)d_in[1];
    const float* Jp = (const float*)d_in[2];
    const float* Jd = (const float*)d_in[3];
    const float* lm = (const float*)d_in[4];

    float* out   = (float*)d_out;
    float* pose  = out;            // [B,6]
    float* depth = out + B_ * 6;   // [B,N]

    dim3 g1(CHUNKS, B_);
    pass1_kernel<<<g1, TPB>>>(r, w, Jp, Jd, lm);
    solve_kernel<<<1, 32>>>(lm, pose);
    dim3 g2((N_ / 2 + 255) / 256, B_);
    pass2_kernel<<<g2, 256>>>(pose, depth);
}

// round 3
// speedup vs baseline: 1.5760x; 1.5760x over previous
#include <cuda_runtime.h>

#define B_ 32
#define N_ 65536
#define CHUNKS 32          // blocks per batch in pass1
#define TPB 256

// Deterministic per-block partials: [b][block][27]  (21 sym H_eff + 6 g_eff)
__device__ float g_part[B_][CHUNKS][27];
// Per-point scratch: [b][n][8] = ti[6] (= inv*H_pd), s (= inv*g_d), pad
__device__ float g_scratch[(size_t)B_ * N_ * 8];

// ---------------------------------------------------------------------------
// Pass 1: single sweep over inputs. Streaming (evict-first) loads so the
// scratch we write stays L2-resident for pass 2. One point per iteration
// (R1 shape: 64 regs, occ ~43%).
// ---------------------------------------------------------------------------
__global__ __launch_bounds__(TPB) void pass1_kernel(
    const float* __restrict__ r, const float* __restrict__ w,
    const float* __restrict__ Jp, const float* __restrict__ Jd,
    const float* __restrict__ lmbda)
{
    const int b = blockIdx.y;
    const float lam = __ldg(lmbda);

    float acc[27];
#pragma unroll
    for (int v = 0; v < 27; v++) acc[v] = 0.f;

    const int   gtid   = blockIdx.x * TPB + threadIdx.x;
    const int   stride = CHUNKS * TPB;
    const size_t base2  = (size_t)b * N_ * 2;
    const size_t base12 = (size_t)b * N_ * 12;

    for (int n = gtid; n < N_; n += stride) {
        float2 rv = __ldcs((const float2*)(r  + base2 + 2 * (size_t)n));
        float2 wv = __ldcs((const float2*)(w  + base2 + 2 * (size_t)n));
        float2 dv = __ldcs((const float2*)(Jd + base2 + 2 * (size_t)n));
        const float4* jp4 = (const float4*)(Jp + base12 + 12 * (size_t)n);
        float4 a0 = __ldcs(jp4 + 0), a1 = __ldcs(jp4 + 1), a2 = __ldcs(jp4 + 2);
        float p0[6] = {a0.x, a0.y, a0.z, a0.w, a1.x, a1.y};
        float p1[6] = {a1.z, a1.w, a2.x, a2.y, a2.z, a2.w};

        const float wd0 = wv.x * dv.x, wd1 = wv.y * dv.y;   // w*Jd per k
        const float wr0 = wv.x * rv.x, wr1 = wv.y * rv.y;   // w*r  per k

        const float Hdd = dv.x * wd0 + dv.y * wd1 + lam;    // sum_k Jd^2 w + lambda
        const float gd  = rv.x * wd0 + rv.y * wd1;          // sum_k Jd w r
        const float inv = 1.f / (Hdd + 1e-8f);
        const float s   = inv * gd;

        float hpd[6], ti[6];
#pragma unroll
        for (int i = 0; i < 6; i++) {
            hpd[i] = p0[i] * wd0 + p1[i] * wd1;             // H_pd_i
            ti[i]  = hpd[i] * inv;
        }

        // scratch for pass 2 (default caching -> L2-resident)
        float4* sc = (float4*)(g_scratch + ((size_t)b * N_ + n) * 8);
        sc[0] = make_float4(ti[0], ti[1], ti[2], ti[3]);
        sc[1] = make_float4(ti[4], ti[5], s, 0.f);

        int c = 0;
#pragma unroll
        for (int i = 0; i < 6; i++) {
            const float qi0 = p0[i] * wv.x, qi1 = p1[i] * wv.y;
#pragma unroll
            for (int j = i; j < 6; j++, c++)
                acc[c] += qi0 * p0[j] + qi1 * p1[j] - ti[i] * hpd[j];
            acc[21 + i] += p0[i] * wr0 + p1[i] * wr1 - hpd[i] * s;
        }
    }

    // warp reduce all 27
#pragma unroll
    for (int v = 0; v < 27; v++)
#pragma unroll
        for (int off = 16; off; off >>= 1)
            acc[v] += __shfl_down_sync(0xffffffffu, acc[v], off);

    __shared__ float swarp[TPB / 32][27];
    const int wid = threadIdx.x >> 5, lid = threadIdx.x & 31;
    if (lid == 0) {
#pragma unroll
        for (int v = 0; v < 27; v++) swarp[wid][v] = acc[v];
    }
    __syncthreads();
    if (threadIdx.x < 27) {
        float s = 0.f;
#pragma unroll
        for (int wv = 0; wv < TPB / 32; wv++) s += swarp[wv][threadIdx.x];
        g_part[b][blockIdx.x][threadIdx.x] = s;  // deterministic, no atomics
    }
}

// ---------------------------------------------------------------------------
// Pass 2 (fused solve): every block redundantly reduces g_part[b] (L2-hot,
// 3.5KB) and solves the 6x6 SPD system in fp32 (no pivoting needed: Schur
// complement of SPD + (lam+eps)I), then computes its slice of delta_depth.
// Blocks with blockIdx.x==0 also write delta_pose.
// ---------------------------------------------------------------------------
#define P2_BLOCKS 32                 // blocks per batch
#define P2_PTS   (N_ / P2_BLOCKS)    // 2048 points per block
#define P2_ITERS (P2_PTS / 256)      // 8 points per thread

__global__ __launch_bounds__(256) void pass2_kernel(
    const float* __restrict__ lmbda, float* __restrict__ out)
{
    const int b = blockIdx.y;
    __shared__ float s27[27];
    __shared__ float dp[6];

    if (threadIdx.x < 27) {
        float s = 0.f;
#pragma unroll
        for (int c = 0; c < CHUNKS; c++) s += g_part[b][c][threadIdx.x];
        s27[threadIdx.x] = s;
    }
    __syncthreads();

    if (threadIdx.x == 0) {
        const float lam = __ldg(lmbda);
        float A[6][7];
        int c = 0;
#pragma unroll
        for (int i = 0; i < 6; i++)
#pragma unroll
            for (int j = i; j < 6; j++, c++) { A[i][j] = s27[c]; A[j][i] = s27[c]; }
#pragma unroll
        for (int i = 0; i < 6; i++) {
            A[i][i] += lam + 1e-4f;      // lambda*I (H_pp) + eps*I (H_eff)
            A[i][6]  = s27[21 + i];      // g_eff
        }
        // no-pivot Gaussian elimination (SPD)
#pragma unroll
        for (int col = 0; col < 6; col++) {
            const float pinv = 1.f / A[col][col];
#pragma unroll
            for (int rr = 0; rr < 6; rr++) {
                if (rr > col) {
                    const float f = A[rr][col] * pinv;
#pragma unroll
                    for (int j = 0; j < 7; j++)
                        if (j >= col) A[rr][j] -= f * A[col][j];
                }
            }
        }
        float x[6];
#pragma unroll
        for (int ii = 5; ii >= 0; ii--) {
            float s = A[ii][6];
#pragma unroll
            for (int j = 0; j < 6; j++)
                if (j > ii) s -= A[ii][j] * x[j];
            x[ii] = s / A[ii][ii];
        }
#pragma unroll
        for (int i = 0; i < 6; i++) dp[i] = x[i];
    }
    __syncthreads();

    if (blockIdx.x == 0 && threadIdx.x < 6)
        out[b * 6 + threadIdx.x] = dp[threadIdx.x];

    float* depth = out + B_ * 6;
    const float d0 = dp[0], d1 = dp[1], d2 = dp[2];
    const float d3 = dp[3], d4 = dp[4], d5 = dp[5];
    const int base = blockIdx.x * P2_PTS;

#pragma unroll
    for (int i = 0; i < P2_ITERS; i++) {
        const int n = base + threadIdx.x + i * 256;
        const float4* sc = (const float4*)(g_scratch + ((size_t)b * N_ + n) * 8);
        float4 a0 = __ldcs(sc + 0), a1 = __ldcs(sc + 1);
        float v = a1.z - (a0.x * d0 + a0.y * d1 + a0.z * d2 +
                          a0.w * d3 + a1.x * d4 + a1.y * d5);
        __stcs(depth + (size_t)b * N_ + n, v);
    }
}

// ---------------------------------------------------------------------------
extern "C" void kernel_launch(void* const* d_in, const int* in_sizes, int n_in,
                              void* d_out, int out_size)
{
    const float* r  = (const float*)d_in[0];
    const float* w  = (const float*)d_in[1];
    const float* Jp = (const float*)d_in[2];
    const float* Jd = (const float*)d_in[3];
    const float* lm = (const float*)d_in[4];

    float* out = (float*)d_out;    // [B,6] pose then [B,N] depth

    dim3 g1(CHUNKS, B_);
    pass1_kernel<<<g1, TPB>>>(r, w, Jp, Jd, lm);
    dim3 g2(P2_BLOCKS, B_);
    pass2_kernel<<<g2, 256>>>(lm, out);
}

// round 4
// speedup vs baseline: 1.7826x; 1.1311x over previous
#include <cuda_runtime.h>
#include <cuda_fp16.h>

#define B_ 32
#define N_ 65536
#define CHUNKS 32          // blocks per batch in pass1
#define TPB 256

// Deterministic per-block partials: [b][block][27]  (21 sym H_eff + 6 g_eff)
__device__ float g_part[B_][CHUNKS][27];

// Per-point scratch, 16 bytes: ti[6] as 3x half2, s as fp32.
// ti = inv_H_dd * H_pd (only ever dotted with the 6-vector dp -> fp16-safe),
// s  = inv_H_dd * g_d  (sets the output scale -> keep fp32).
struct __align__(16) Scr { __half2 t01, t23, t45; float s; };
__device__ Scr g_scratch[(size_t)B_ * N_];

// ---------------------------------------------------------------------------
// Pass 1: single sweep over inputs (streaming/evict-first loads). Accumulates
// the Schur-reduced 6x6 system per batch in fp32 and writes 16B/point scratch.
// ---------------------------------------------------------------------------
__global__ __launch_bounds__(TPB) void pass1_kernel(
    const float* __restrict__ r, const float* __restrict__ w,
    const float* __restrict__ Jp, const float* __restrict__ Jd,
    const float* __restrict__ lmbda)
{
    const int b = blockIdx.y;
    const float lam = __ldg(lmbda);

    float acc[27];
#pragma unroll
    for (int v = 0; v < 27; v++) acc[v] = 0.f;

    const int   gtid   = blockIdx.x * TPB + threadIdx.x;
    const int   stride = CHUNKS * TPB;
    const size_t base2  = (size_t)b * N_ * 2;
    const size_t base12 = (size_t)b * N_ * 12;

    for (int n = gtid; n < N_; n += stride) {
        float2 rv = __ldcs((const float2*)(r  + base2 + 2 * (size_t)n));
        float2 wv = __ldcs((const float2*)(w  + base2 + 2 * (size_t)n));
        float2 dv = __ldcs((const float2*)(Jd + base2 + 2 * (size_t)n));
        const float4* jp4 = (const float4*)(Jp + base12 + 12 * (size_t)n);
        float4 a0 = __ldcs(jp4 + 0), a1 = __ldcs(jp4 + 1), a2 = __ldcs(jp4 + 2);
        float p0[6] = {a0.x, a0.y, a0.z, a0.w, a1.x, a1.y};
        float p1[6] = {a1.z, a1.w, a2.x, a2.y, a2.z, a2.w};

        const float wd0 = wv.x * dv.x, wd1 = wv.y * dv.y;   // w*Jd per k
        const float wr0 = wv.x * rv.x, wr1 = wv.y * rv.y;   // w*r  per k

        const float Hdd = dv.x * wd0 + dv.y * wd1 + lam;    // sum_k Jd^2 w + lambda
        const float gd  = rv.x * wd0 + rv.y * wd1;          // sum_k Jd w r
        const float inv = 1.f / (Hdd + 1e-8f);
        const float s   = inv * gd;

        float hpd[6], ti[6];
#pragma unroll
        for (int i = 0; i < 6; i++) {
            hpd[i] = p0[i] * wd0 + p1[i] * wd1;             // H_pd_i
            ti[i]  = hpd[i] * inv;
        }

        // 16B compressed scratch (single STG.128)
        Scr sc;
        sc.t01 = __floats2half2_rn(ti[0], ti[1]);
        sc.t23 = __floats2half2_rn(ti[2], ti[3]);
        sc.t45 = __floats2half2_rn(ti[4], ti[5]);
        sc.s   = s;
        g_scratch[(size_t)b * N_ + n] = sc;

        int c = 0;
#pragma unroll
        for (int i = 0; i < 6; i++) {
            const float qi0 = p0[i] * wv.x, qi1 = p1[i] * wv.y;
#pragma unroll
            for (int j = i; j < 6; j++, c++)
                acc[c] += qi0 * p0[j] + qi1 * p1[j] - ti[i] * hpd[j];
            acc[21 + i] += p0[i] * wr0 + p1[i] * wr1 - hpd[i] * s;
        }
    }

    // warp reduce all 27
#pragma unroll
    for (int v = 0; v < 27; v++)
#pragma unroll
        for (int off = 16; off; off >>= 1)
            acc[v] += __shfl_down_sync(0xffffffffu, acc[v], off);

    __shared__ float swarp[TPB / 32][27];
    const int wid = threadIdx.x >> 5, lid = threadIdx.x & 31;
    if (lid == 0) {
#pragma unroll
        for (int v = 0; v < 27; v++) swarp[wid][v] = acc[v];
    }
    __syncthreads();
    if (threadIdx.x < 27) {
        float s = 0.f;
#pragma unroll
        for (int wv = 0; wv < TPB / 32; wv++) s += swarp[wv][threadIdx.x];
        g_part[b][blockIdx.x][threadIdx.x] = s;  // deterministic, no atomics
    }
}

// ---------------------------------------------------------------------------
// Pass 2 (fused solve): every block redundantly reduces g_part[b] (L2-hot)
// and solves the 6x6 SPD system in fp32 (Schur complement of SPD + (lam+eps)I
// -> no pivoting), then computes its slice of delta_depth.
// ---------------------------------------------------------------------------
#define P2_BLOCKS 32                 // blocks per batch
#define P2_PTS   (N_ / P2_BLOCKS)    // 2048 points per block
#define P2_ITERS (P2_PTS / 256)      // 8 points per thread

__global__ __launch_bounds__(256) void pass2_kernel(
    const float* __restrict__ lmbda, float* __restrict__ out)
{
    const int b = blockIdx.y;
    __shared__ float s27[27];
    __shared__ float dp[6];

    if (threadIdx.x < 27) {
        float s = 0.f;
#pragma unroll
        for (int c = 0; c < CHUNKS; c++) s += g_part[b][c][threadIdx.x];
        s27[threadIdx.x] = s;
    }
    __syncthreads();

    if (threadIdx.x == 0) {
        const float lam = __ldg(lmbda);
        float A[6][7];
        int c = 0;
#pragma unroll
        for (int i = 0; i < 6; i++)
#pragma unroll
            for (int j = i; j < 6; j++, c++) { A[i][j] = s27[c]; A[j][i] = s27[c]; }
#pragma unroll
        for (int i = 0; i < 6; i++) {
            A[i][i] += lam + 1e-4f;      // lambda*I (H_pp) + eps*I (H_eff)
            A[i][6]  = s27[21 + i];      // g_eff
        }
#pragma unroll
        for (int col = 0; col < 6; col++) {
            const float pinv = 1.f / A[col][col];
#pragma unroll
            for (int rr = 0; rr < 6; rr++) {
                if (rr > col) {
                    const float f = A[rr][col] * pinv;
#pragma unroll
                    for (int j = 0; j < 7; j++)
                        if (j >= col) A[rr][j] -= f * A[col][j];
                }
            }
        }
        float x[6];
#pragma unroll
        for (int ii = 5; ii >= 0; ii--) {
            float s = A[ii][6];
#pragma unroll
            for (int j = 0; j < 6; j++)
                if (j > ii) s -= A[ii][j] * x[j];
            x[ii] = s / A[ii][ii];
        }
#pragma unroll
        for (int i = 0; i < 6; i++) dp[i] = x[i];
    }
    __syncthreads();

    if (blockIdx.x == 0 && threadIdx.x < 6)
        out[b * 6 + threadIdx.x] = dp[threadIdx.x];

    float* depth = out + B_ * 6;
    const float d0 = dp[0], d1 = dp[1], d2 = dp[2];
    const float d3 = dp[3], d4 = dp[4], d5 = dp[5];
    const int base = blockIdx.x * P2_PTS;

#pragma unroll
    for (int i = 0; i < P2_ITERS; i++) {
        const int n = base + threadIdx.x + i * 256;
        const uint4 raw = __ldcs((const uint4*)(g_scratch + (size_t)b * N_ + n));
        Scr sc;
        *(uint4*)&sc = raw;
        const float2 f01 = __half22float2(sc.t01);
        const float2 f23 = __half22float2(sc.t23);
        const float2 f45 = __half22float2(sc.t45);
        float v = sc.s - (f01.x * d0 + f01.y * d1 + f23.x * d2 +
                          f23.y * d3 + f45.x * d4 + f45.y * d5);
        __stcs(depth + (size_t)b * N_ + n, v);
    }
}

// ---------------------------------------------------------------------------
extern "C" void kernel_launch(void* const* d_in, const int* in_sizes, int n_in,
                              void* d_out, int out_size)
{
    const float* r  = (const float*)d_in[0];
    const float* w  = (const float*)d_in[1];
    const float* Jp = (const float*)d_in[2];
    const float* Jd = (const float*)d_in[3];
    const float* lm = (const float*)d_in[4];

    float* out = (float*)d_out;    // [B,6] pose then [B,N] depth

    dim3 g1(CHUNKS, B_);
    pass1_kernel<<<g1, TPB>>>(r, w, Jp, Jd, lm);
    dim3 g2(P2_BLOCKS, B_);
    pass2_kernel<<<g2, 256>>>(lm, out);
}